// round 3
// baseline (speedup 1.0000x reference)
#include <cuda_runtime.h>
#include <cstdint>
#include <cstddef>

// ---------------- Problem constants ----------------
// spk: [65536, 1024] fp32 (A, K-major), W: [1024, 1024] fp32 (B rows = out dim, K-major),
// b: [1024], beta: [1024].
// out: out_seq [65536 x 1024] then final_mem [65536] at float offset 67108864.
#define M_TOTAL 65536
#define N_TOTAL 1024
#define K_TOTAL 1024

#define BM 128
#define BN 256
#define BK 32                      // 32 floats = 128 B per smem row
#define KC (K_TOTAL / BK)          // 32 chunks
#define NSTG 3
#define A_BYTES (BM * 128)         // 16 KB
#define B_BYTES (BN * 128)         // 32 KB
#define STG_BYTES (A_BYTES + B_BYTES)   // 48 KB
#define SMEM_DYN (1024 + NSTG * STG_BYTES)

// ---------------- PTX helpers (baseline features only: sm_80-class) ----------------
__device__ __forceinline__ uint32_t smem_u32(const void* p) {
    uint32_t r;
    asm("{ .reg .u64 t; cvta.to.shared.u64 t, %1; cvt.u32.u64 %0, t; }" : "=r"(r) : "l"(p));
    return r;
}
__device__ __forceinline__ void cp16(uint32_t dst, const void* src) {
    asm volatile("cp.async.cg.shared.global [%0], [%1], 16;"
                 :: "r"(dst), "l"(__cvta_generic_to_global(src)) : "memory");
}
#define CP_COMMIT() asm volatile("cp.async.commit_group;" ::: "memory")
template <int N>
__device__ __forceinline__ void cp_wait() {
    asm volatile("cp.async.wait_group %0;" :: "n"(N) : "memory");
}
__device__ __forceinline__ void ldmatrix_x4(uint32_t* r, uint32_t addr) {
    asm volatile("ldmatrix.sync.aligned.m8n8.x4.shared.b16 {%0,%1,%2,%3}, [%4];"
                 : "=r"(r[0]), "=r"(r[1]), "=r"(r[2]), "=r"(r[3]) : "r"(addr));
}
__device__ __forceinline__ uint32_t f2tf32(uint32_t bits) {
    uint32_t o;
    asm("cvt.rna.tf32.f32 %0, %1;" : "=r"(o) : "f"(__uint_as_float(bits)));
    return o;
}
__device__ __forceinline__ void mma_tf32(float* d, const uint32_t* a,
                                         uint32_t b0, uint32_t b1) {
    asm volatile(
        "mma.sync.aligned.m16n8k8.row.col.f32.tf32.tf32.f32 "
        "{%0,%1,%2,%3}, {%4,%5,%6,%7}, {%8,%9}, {%0,%1,%2,%3};"
        : "+f"(d[0]), "+f"(d[1]), "+f"(d[2]), "+f"(d[3])
        : "r"(a[0]), "r"(a[1]), "r"(a[2]), "r"(a[3]), "r"(b0), "r"(b1));
}

// ---------------- producer: gmem -> swizzled smem ----------------
// A tile: 128 rows x 32 floats; B tile: 256 rows x 32 floats. Row = 128B, SW128 swizzle:
// 16B-granule g stored at g ^ (row & 7).
__device__ __forceinline__ void load_chunk(int tid, uint32_t stage_base, int kc,
                                           const float* __restrict__ A,
                                           const float* __restrict__ W,
                                           int m_base, int n_base) {
    const float* gA = A + (size_t)m_base * K_TOTAL + kc * BK;
    const float* gB = W + (size_t)n_base * K_TOTAL + kc * BK;
    uint32_t sA = stage_base;
    uint32_t sB = stage_base + A_BYTES;
#pragma unroll
    for (int i = 0; i < 4; ++i) {                    // A: 1024 granules / 256 thr
        int idx = tid + i * 256;
        int row = idx >> 3, g = idx & 7;
        uint32_t sw = row * 128 + ((g ^ (row & 7)) << 4);
        cp16(sA + sw, gA + (size_t)row * K_TOTAL + g * 4);
    }
#pragma unroll
    for (int i = 0; i < 8; ++i) {                    // B: 2048 granules / 256 thr
        int idx = tid + i * 256;
        int row = idx >> 3, g = idx & 7;
        uint32_t sw = row * 128 + ((g ^ (row & 7)) << 4);
        cp16(sB + sw, gB + (size_t)row * K_TOTAL + g * 4);
    }
}

// ---------------- GEMM: cur = spk @ W^T + b -> out_seq region ----------------
__global__ void __launch_bounds__(256, 1)
gemm_tf32_kernel(const float* __restrict__ A, const float* __restrict__ W,
                 const float* __restrict__ bias, float* __restrict__ out) {
    extern __shared__ char smem[];
    const int tid = threadIdx.x;
    const int lane = tid & 31;
    const int wid = tid >> 5;
    const int warp_m = wid & 1;        // 2 warp-rows  (64 M each)
    const int warp_n = wid >> 1;       // 4 warp-cols  (64 N each)
    const int n_base = blockIdx.x * BN;
    const int m_base = blockIdx.y * BM;

    uint32_t AL = (smem_u32(smem) + 1023) & ~1023u;

    // ldmatrix row constants (same formula for A m-tiles and B n-pairs):
    // row(t) = warp_dim*64 + t*16 + ((lane>>3)&1)*8 + (lane&7)
    const int lrow = ((lane >> 3) & 1) * 8 + (lane & 7);
    const int ghi = lane >> 4;         // granule high bit from matrix index 2/3
    uint32_t aOff[4], aSw[4], bOff[4], bSw[4];
#pragma unroll
    for (int t = 0; t < 4; ++t) {
        int ra = warp_m * 64 + t * 16 + lrow;
        int rb = warp_n * 64 + t * 16 + lrow;
        aOff[t] = ra * 128; aSw[t] = ra & 7;
        bOff[t] = rb * 128; bSw[t] = rb & 7;
    }

    float acc[4][8][4];
#pragma unroll
    for (int mt = 0; mt < 4; ++mt)
#pragma unroll
        for (int nt = 0; nt < 8; ++nt)
#pragma unroll
            for (int i = 0; i < 4; ++i) acc[mt][nt][i] = 0.0f;

    // prologue: prefetch chunks 0, 1
#pragma unroll
    for (int c = 0; c < NSTG - 1; ++c) {
        load_chunk(tid, AL + c * STG_BYTES, c, A, W, m_base, n_base);
        CP_COMMIT();
    }

    for (int k = 0; k < KC; ++k) {
        cp_wait<NSTG - 2>();           // chunk k resident
        __syncthreads();

        int pc = k + NSTG - 1;
        if (pc < KC)
            load_chunk(tid, AL + (pc % NSTG) * STG_BYTES, pc, A, W, m_base, n_base);
        CP_COMMIT();

        uint32_t sA = AL + (k % NSTG) * STG_BYTES;
        uint32_t sB = sA + A_BYTES;
#pragma unroll
        for (int ks = 0; ks < 4; ++ks) {           // 4 k8 steps per 32-chunk
            const int g = ks * 2 + ghi;
            uint32_t af[4][4], bf[4][4];
#pragma unroll
            for (int t = 0; t < 4; ++t)
                ldmatrix_x4(af[t], sA + aOff[t] + ((g ^ aSw[t]) << 4));
#pragma unroll
            for (int t = 0; t < 4; ++t)
                ldmatrix_x4(bf[t], sB + bOff[t] + ((g ^ bSw[t]) << 4));
            // round-to-nearest tf32 (unbiased; raw truncation biases the dot by ~1e-2)
#pragma unroll
            for (int t = 0; t < 4; ++t)
#pragma unroll
                for (int i = 0; i < 4; ++i) {
                    af[t][i] = f2tf32(af[t][i]);
                    bf[t][i] = f2tf32(bf[t][i]);
                }
#pragma unroll
            for (int mt = 0; mt < 4; ++mt)
#pragma unroll
                for (int nt = 0; nt < 8; ++nt) {
                    int i = nt >> 1, odd = nt & 1;
                    mma_tf32(acc[mt][nt], af[mt], bf[i][odd], bf[i][2 + odd]);
                }
        }
        __syncthreads();   // before next iter's producer reuses a drained stage
    }

    // ---------------- epilogue: bias + direct float2 stores ----------------
    float2 bv[8];
    const float2* b2 = reinterpret_cast<const float2*>(bias);
#pragma unroll
    for (int nt = 0; nt < 8; ++nt)
        bv[nt] = b2[(n_base + warp_n * 64 + nt * 8) / 2 + (lane & 3)];

#pragma unroll
    for (int mt = 0; mt < 4; ++mt) {
        int r0 = m_base + warp_m * 64 + mt * 16 + (lane >> 2);
#pragma unroll
        for (int nt = 0; nt < 8; ++nt) {
            int col = n_base + warp_n * 64 + nt * 8 + (lane & 3) * 2;
            float2 v0 = make_float2(acc[mt][nt][0] + bv[nt].x, acc[mt][nt][1] + bv[nt].y);
            float2 v1 = make_float2(acc[mt][nt][2] + bv[nt].x, acc[mt][nt][3] + bv[nt].y);
            *reinterpret_cast<float2*>(out + (size_t)r0 * N_TOTAL + col) = v0;
            *reinterpret_cast<float2*>(out + (size_t)(r0 + 8) * N_TOTAL + col) = v1;
        }
    }
}

// ---------------- Scan: mem_t = beta*mem + cur_t, in place over out_seq ----------------
__global__ void __launch_bounds__(256)
scan_kernel(float* __restrict__ out, const float* __restrict__ mem0,
            const float* __restrict__ beta) {
    int c = blockIdx.x * 256 + threadIdx.x;      // chain id: n*1024 + o
    float bt = __ldg(beta + (c & 1023));
    float m = __ldg(mem0 + c);
    float* p = out + c;
#pragma unroll 8
    for (int l = 0; l < 1024; ++l) {
        float v = p[(size_t)l << 16];
        m = fmaf(bt, m, v);
        p[(size_t)l << 16] = m;
    }
    out[(size_t)67108864 + c] = m;               // final_mem
}

// ---------------- launch ----------------
extern "C" void kernel_launch(void* const* d_in, const int* in_sizes, int n_in,
                              void* d_out, int out_size) {
    const float* spk  = (const float*)d_in[0];
    const float* mem0 = (const float*)d_in[1];
    const float* W    = (const float*)d_in[2];
    const float* bias = (const float*)d_in[3];
    const float* beta = (const float*)d_in[4];
    float* out = (float*)d_out;

    cudaFuncSetAttribute(gemm_tf32_kernel,
                         cudaFuncAttributeMaxDynamicSharedMemorySize, SMEM_DYN);

    dim3 grid(N_TOTAL / BN, M_TOTAL / BM);       // (4, 512), x fastest for W/L2 reuse
    gemm_tf32_kernel<<<grid, 256, SMEM_DYN>>>(spk, W, bias, out);
    scan_kernel<<<65536 / 256, 256>>>(out, mem0, beta);
}